// round 8
// baseline (speedup 1.0000x reference)
#include <cuda_runtime.h>
#include <cuda_bf16.h>
#include <cstdint>

#define NND 50000
#define NPAD 50048
#define NE  800000
#define DD  256
#define K2  512
#define NBP 391              // BN partials = gemm gridDim.x

// GEMM tiling
#define BM 128
#define BN 128
#define CHUNKS 24                 // 3 bf16-split products x (512/64)
#define SROW 144                  // smem row stride bytes (128 data + 16 pad)
#define BUFBYTES (128 * SROW)     // 18432
#define NSTAGE 3
#define STAGEBYTES (2 * BUFBYTES)            // A + B per stage
#define GEMM_SMEM (NSTAGE * STAGEBYTES)      // 110592

// ---------------- static device scratch --------------------------------------
__device__ __align__(16) float g_h[NND * DD];
__device__ int   g_cnt[NND];
__device__ int   g_rowptr[NND + 1];
__device__ int   g_cursor[NND];
__device__ int   g_csrc[NE];
__device__ float g_invdeg[NND];
__device__ __align__(16) float g_psum[NBP * DD];
__device__ __align__(16) float g_psq[NBP * DD];
__device__ __align__(16) float g_scale[DD];
__device__ __align__(16) float g_shift[DD];
// bf16 split A = [split(agg) | split(x)], rows padded to NPAD (pad rows stay 0)
__device__ __align__(16) __nv_bfloat16 g_ahi[(size_t)NPAD * K2];
__device__ __align__(16) __nv_bfloat16 g_alo[(size_t)NPAD * K2];
// B[n][k] = Wcat[k][n] transposed + split, per layer
__device__ __align__(16) __nv_bfloat16 g_bhi[3][DD * K2];
__device__ __align__(16) __nv_bfloat16 g_blo[3][DD * K2];

__device__ __forceinline__ int clampi(int v, int lo, int hi) {
    return v < lo ? lo : (v > hi ? hi : v);
}
__device__ __forceinline__ uint32_t smem_u32(const void* p) {
    uint32_t a;
    asm("{ .reg .u64 t; cvta.to.shared.u64 t, %1; cvt.u32.u64 %0, t; }" : "=r"(a) : "l"(p));
    return a;
}
__device__ __forceinline__ void ldsm_x4(uint32_t* r, uint32_t addr) {
    asm volatile("ldmatrix.sync.aligned.m8n8.x4.shared.b16 {%0,%1,%2,%3}, [%4];"
        : "=r"(r[0]), "=r"(r[1]), "=r"(r[2]), "=r"(r[3]) : "r"(addr));
}
__device__ __forceinline__ void mma_bf16(float* c, const uint32_t* a,
                                         uint32_t b0, uint32_t b1) {
    asm volatile(
        "mma.sync.aligned.m16n8k16.row.col.f32.bf16.bf16.f32 "
        "{%0,%1,%2,%3}, {%4,%5,%6,%7}, {%8,%9}, {%0,%1,%2,%3};"
        : "+f"(c[0]), "+f"(c[1]), "+f"(c[2]), "+f"(c[3])
        : "r"(a[0]), "r"(a[1]), "r"(a[2]), "r"(a[3]), "r"(b0), "r"(b1));
}
#define CP_ASYNC16(dst, src) \
    asm volatile("cp.async.ca.shared.global [%0], [%1], 16;" :: "r"(dst), "l"(src) : "memory")
#define CP_COMMIT() asm volatile("cp.async.commit_group;" ::: "memory")
#define CP_WAIT(n)  asm volatile("cp.async.wait_group %0;" :: "n"(n) : "memory")

// split helper: v -> (hi, lo) bf16 pair
__device__ __forceinline__ void bf16_split4(const float* v, __nv_bfloat16* hi,
                                            __nv_bfloat16* lo) {
    #pragma unroll
    for (int i = 0; i < 4; i++) {
        hi[i] = __float2bfloat16(v[i]);
        lo[i] = __float2bfloat16(v[i] - __bfloat162float(hi[i]));
    }
}

// ---------------- CSR build ---------------------------------------------------
__global__ void k_hist(const int* __restrict__ dst) {
    int e = blockIdx.x * blockDim.x + threadIdx.x;
    if (e < NE) atomicAdd(&g_cnt[clampi(dst[e], 0, NND - 1)], 1);
}
__global__ void k_scan() {
    __shared__ int s[1024];
    __shared__ int carry;
    int tid = threadIdx.x;
    if (tid == 0) carry = 0;
    __syncthreads();
    for (int base = 0; base < NND; base += 1024) {
        int i = base + tid;
        int v = (i < NND) ? g_cnt[i] : 0;
        s[tid] = v;
        __syncthreads();
        #pragma unroll
        for (int off = 1; off < 1024; off <<= 1) {
            int t = 0;
            if (tid >= off) t = s[tid - off];
            __syncthreads();
            if (tid >= off) s[tid] += t;
            __syncthreads();
        }
        if (i < NND) {
            int rp = carry + s[tid] - v;
            g_rowptr[i] = rp;
            g_cursor[i] = rp;
            g_invdeg[i] = 1.0f / (float)max(v, 1);
        }
        __syncthreads();
        if (tid == 0) carry += s[1023];
        __syncthreads();
    }
    if (tid == 0) g_rowptr[NND] = carry;
}
__global__ void k_scatter(const int* __restrict__ src, const int* __restrict__ dst) {
    int e = blockIdx.x * blockDim.x + threadIdx.x;
    if (e < NE) {
        int d = clampi(dst[e], 0, NND - 1);
        int pos = atomicAdd(&g_cursor[d], 1);
        if (pos >= 0 && pos < NE) g_csrc[pos] = clampi(src[e], 0, NND - 1);
    }
}

// ------ layer 0 aggregate: gather raw x, split agg (cols 0-255) + x (256-511) --
__global__ void __launch_bounds__(256) k_aggregate0(const float* __restrict__ xin) {
    int node = blockIdx.x * 4 + (threadIdx.x >> 6);
    int lane = threadIdx.x & 63;
    if (node >= NND) return;
    int beg = g_rowptr[node];
    int end = g_rowptr[node + 1];
    float4 acc = make_float4(0.f, 0.f, 0.f, 0.f);
    for (int e = beg; e < end; e++) {
        int s = g_csrc[e];
        float4 v = *(const float4*)(xin + (size_t)s * DD + lane * 4);
        acc.x += v.x; acc.y += v.y; acc.z += v.z; acc.w += v.w;
    }
    float id = g_invdeg[node];
    float a[4] = { acc.x * id, acc.y * id, acc.z * id, acc.w * id };
    __nv_bfloat16 hi[4], lo[4];
    bf16_split4(a, hi, lo);
    size_t o = (size_t)node * K2 + lane * 4;
    *(uint2*)(g_ahi + o) = *(const uint2*)hi;
    *(uint2*)(g_alo + o) = *(const uint2*)lo;
    float4 xv = *(const float4*)(xin + (size_t)node * DD + lane * 4);
    float xf[4] = { xv.x, xv.y, xv.z, xv.w };
    bf16_split4(xf, hi, lo);
    *(uint2*)(g_ahi + o + DD) = *(const uint2*)hi;
    *(uint2*)(g_alo + o + DD) = *(const uint2*)lo;
}

// ------ layers 1,2 aggregate: gather h, apply BN+ReLU per edge, split ----------
__global__ void __launch_bounds__(256) k_aggregate_fused() {
    int node = blockIdx.x * 4 + (threadIdx.x >> 6);
    int lane = threadIdx.x & 63;
    if (node >= NND) return;
    float4 sc = *(const float4*)&g_scale[lane * 4];
    float4 sh = *(const float4*)&g_shift[lane * 4];
    int beg = g_rowptr[node];
    int end = g_rowptr[node + 1];
    float4 acc = make_float4(0.f, 0.f, 0.f, 0.f);
    for (int e = beg; e < end; e++) {
        int s = g_csrc[e];
        float4 v = *(const float4*)(g_h + (size_t)s * DD + lane * 4);
        acc.x += fmaxf(0.f, fmaf(v.x, sc.x, sh.x));
        acc.y += fmaxf(0.f, fmaf(v.y, sc.y, sh.y));
        acc.z += fmaxf(0.f, fmaf(v.z, sc.z, sh.z));
        acc.w += fmaxf(0.f, fmaf(v.w, sc.w, sh.w));
    }
    float id = g_invdeg[node];
    float a[4] = { acc.x * id, acc.y * id, acc.z * id, acc.w * id };
    __nv_bfloat16 hi[4], lo[4];
    bf16_split4(a, hi, lo);
    size_t o = (size_t)node * K2 + lane * 4;
    *(uint2*)(g_ahi + o) = *(const uint2*)hi;
    *(uint2*)(g_alo + o) = *(const uint2*)lo;
    // own-node x = relu(h*sc+sh), split into cols 256-511
    float4 hv = *(const float4*)(g_h + (size_t)node * DD + lane * 4);
    float xf[4];
    xf[0] = fmaxf(0.f, fmaf(hv.x, sc.x, sh.x));
    xf[1] = fmaxf(0.f, fmaf(hv.y, sc.y, sh.y));
    xf[2] = fmaxf(0.f, fmaf(hv.z, sc.z, sh.z));
    xf[3] = fmaxf(0.f, fmaf(hv.w, sc.w, sh.w));
    bf16_split4(xf, hi, lo);
    *(uint2*)(g_ahi + o + DD) = *(const uint2*)hi;
    *(uint2*)(g_alo + o + DD) = *(const uint2*)lo;
}

// ---------------- weight transpose + split (all 3 layers, once) ----------------
__global__ void __launch_bounds__(256) k_mkB(const float* __restrict__ Wl,
                                             const float* __restrict__ Wr) {
    int idx = blockIdx.x * 256 + threadIdx.x;
    int l = idx / (DD * K2);
    int rem = idx % (DD * K2);
    int n = rem / K2;
    int k = rem % K2;
    float v = (k < DD) ? Wl[(size_t)l * DD * DD + (size_t)k * DD + n]
                       : Wr[(size_t)l * DD * DD + (size_t)(k - DD) * DD + n];
    __nv_bfloat16 hi = __float2bfloat16(v);
    __nv_bfloat16 lo = __float2bfloat16(v - __bfloat162float(hi));
    g_bhi[l][n * K2 + k] = hi;
    g_blo[l][n * K2 + k] = lo;
}

// -------- mma.sync GEMM, 3-stage cp.async pipeline, 1 barrier/chunk ------------
__global__ void __launch_bounds__(256, 2) k_gemm_mma(int layer) {
    extern __shared__ char smem[];

    const int tid  = threadIdx.x;
    const int wid  = tid >> 5;
    const int lane = tid & 31;
    const int wm   = wid >> 1;          // 0..3
    const int wn   = wid & 1;           // 0..1
    const int row0 = blockIdx.x * BM;
    const int col0 = blockIdx.y * BN;

    const __nv_bfloat16* const Asrc[3] = { g_ahi, g_alo, g_ahi };
    const __nv_bfloat16* const Bsrc[3] = { g_bhi[layer], g_bhi[layer], g_blo[layer] };

    const int lrow = tid >> 1;                 // 0..127
    const int lseg = (tid & 1) * 4;            // 16B-seg base (0 or 4)

    float acc[2][8][4];
    #pragma unroll
    for (int i = 0; i < 2; i++)
        #pragma unroll
        for (int j = 0; j < 8; j++)
            #pragma unroll
            for (int q = 0; q < 4; q++) acc[i][j][q] = 0.f;

    // ldmatrix base offsets within a stage
    uint32_t aOff, bOff;
    {
        int am = wm * 32 + (lane & 15);
        int ak = (lane >> 4) * 8;
        int bn = wn * 64 + ((lane >> 4) << 3) + (lane & 7);
        int bk = ((lane >> 3) & 1) * 8;
        aOff = (uint32_t)(am * SROW + ak * 2);
        bOff = (uint32_t)(BUFBYTES + bn * SROW + bk * 2);
    }
    const uint32_t sbase = smem_u32(smem);

    auto load_chunk = [&](int c) {
        int p   = c >> 3;
        int kc  = (c & 7) * 64;
        int st  = c % NSTAGE;
        const __nv_bfloat16* Ag = Asrc[p] + (size_t)(row0 + lrow) * K2 + kc + lseg * 8;
        const __nv_bfloat16* Bg = Bsrc[p] + (size_t)(col0 + lrow) * K2 + kc + lseg * 8;
        uint32_t As = sbase + st * STAGEBYTES + lrow * SROW + lseg * 16;
        uint32_t Bs = As + BUFBYTES;
        #pragma unroll
        for (int i = 0; i < 4; i++) {
            CP_ASYNC16(As + i * 16, Ag + i * 8);
            CP_ASYNC16(Bs + i * 16, Bg + i * 8);
        }
        CP_COMMIT();
    };

    load_chunk(0);
    load_chunk(1);
    for (int c = 0; c < CHUNKS; ++c) {
        if (c + 2 < CHUNKS) CP_WAIT(1); else CP_WAIT(0);
        __syncthreads();              // publishes chunk c; proves chunk c-1 consumed
        if (c + 2 < CHUNKS) load_chunk(c + 2);

        uint32_t stB = sbase + (c % NSTAGE) * STAGEBYTES;
        #pragma unroll
        for (int kk = 0; kk < 64; kk += 16) {
            uint32_t a[2][4], b[4][4];
            #pragma unroll
            for (int mt = 0; mt < 2; mt++)
                ldsm_x4(a[mt], stB + aOff + (mt * 16) * SROW + kk * 2);
            #pragma unroll
            for (int nt = 0; nt < 4; nt++)
                ldsm_x4(b[nt], stB + bOff + (nt * 16) * SROW + kk * 2);
            #pragma unroll
            for (int mi = 0; mi < 2; mi++)
                #pragma unroll
                for (int nj = 0; nj < 8; nj++)
                    mma_bf16(acc[mi][nj], a[mi],
                             b[nj >> 1][(nj & 1) * 2], b[nj >> 1][(nj & 1) * 2 + 1]);
        }
    }

    // --- write h (rows < NND) ---
    const int g  = lane >> 2;
    const int tg = lane & 3;
    #pragma unroll
    for (int mi = 0; mi < 2; mi++) {
        int r1 = row0 + wm * 32 + mi * 16 + g;
        int r2 = r1 + 8;
        #pragma unroll
        for (int nj = 0; nj < 8; nj++) {
            int cix = col0 + wn * 64 + nj * 8 + tg * 2;
            if (r1 < NND) {
                float2 o = { acc[mi][nj][0], acc[mi][nj][1] };
                *(float2*)(g_h + (size_t)r1 * DD + cix) = o;
            }
            if (r2 < NND) {
                float2 o = { acc[mi][nj][2], acc[mi][nj][3] };
                *(float2*)(g_h + (size_t)r2 * DD + cix) = o;
            }
        }
    }

    // --- BN partials: per-CTA column sum & sumsq (pad rows contribute 0) ---
    __syncthreads();                       // reuse stage smem for reduction
    float* sred  = (float*)smem;           // [4][128]
    float* sqred = (float*)(smem + 2048);  // [4][128]
    #pragma unroll
    for (int nj = 0; nj < 8; nj++) {
        float s0 = acc[0][nj][0] + acc[0][nj][2] + acc[1][nj][0] + acc[1][nj][2];
        float s1 = acc[0][nj][1] + acc[0][nj][3] + acc[1][nj][1] + acc[1][nj][3];
        float q0 = acc[0][nj][0]*acc[0][nj][0] + acc[0][nj][2]*acc[0][nj][2]
                 + acc[1][nj][0]*acc[1][nj][0] + acc[1][nj][2]*acc[1][nj][2];
        float q1 = acc[0][nj][1]*acc[0][nj][1] + acc[0][nj][3]*acc[0][nj][3]
                 + acc[1][nj][1]*acc[1][nj][1] + acc[1][nj][3]*acc[1][nj][3];
        #pragma unroll
        for (int off = 16; off >= 4; off >>= 1) {
            s0 += __shfl_down_sync(0xFFFFFFFF, s0, off);
            s1 += __shfl_down_sync(0xFFFFFFFF, s1, off);
            q0 += __shfl_down_sync(0xFFFFFFFF, q0, off);
            q1 += __shfl_down_sync(0xFFFFFFFF, q1, off);
        }
        if (lane < 4) {
            int c = wn * 64 + nj * 8 + lane * 2;
            sred[wm * 128 + c]      = s0;
            sred[wm * 128 + c + 1]  = s1;
            sqred[wm * 128 + c]     = q0;
            sqred[wm * 128 + c + 1] = q1;
        }
    }
    __syncthreads();
    if (tid < 128) {
        float s = sred[tid] + sred[128 + tid] + sred[256 + tid] + sred[384 + tid];
        float q = sqred[tid] + sqred[128 + tid] + sqred[256 + tid] + sqred[384 + tid];
        g_psum[blockIdx.x * DD + col0 + tid] = s;
        g_psq [blockIdx.x * DD + col0 + tid] = q;
    }
}

// ---------------- BN finalize: one block per column -------------------------------
__global__ void __launch_bounds__(128) k_bnfinal(const float* __restrict__ gamma,
                                                 const float* __restrict__ beta) {
    __shared__ float ss[128], sq[128];
    int j = blockIdx.x;          // column
    int t = threadIdx.x;
    float s = 0.f, q = 0.f;
    for (int b = t; b < NBP; b += 128) {
        s += g_psum[b * DD + j];
        q += g_psq[b * DD + j];
    }
    ss[t] = s; sq[t] = q;
    __syncthreads();
    #pragma unroll
    for (int off = 64; off > 0; off >>= 1) {
        if (t < off) { ss[t] += ss[t + off]; sq[t] += sq[t + off]; }
        __syncthreads();
    }
    if (t == 0) {
        float inv_n = 1.0f / (float)NND;
        float mu  = ss[0] * inv_n;
        float var = sq[0] * inv_n - mu * mu;
        float sc  = gamma[j] * rsqrtf(var + 1e-5f);
        g_scale[j] = sc;
        g_shift[j] = beta[j] - mu * sc;
    }
}

// ---------------- final output: BN + ReLU -> d_out ---------------------------------
__global__ void __launch_bounds__(256) k_apply_out(float* __restrict__ dout) {
    int idx = blockIdx.x * blockDim.x + threadIdx.x;   // float4 index
    int c4 = idx & 63;
    float4 h  = *(const float4*)&g_h[(size_t)idx * 4];
    float4 sc = *(const float4*)&g_scale[c4 * 4];
    float4 sh = *(const float4*)&g_shift[c4 * 4];
    float4 r;
    r.x = fmaxf(0.f, fmaf(h.x, sc.x, sh.x));
    r.y = fmaxf(0.f, fmaf(h.y, sc.y, sh.y));
    r.z = fmaxf(0.f, fmaf(h.z, sc.z, sh.z));
    r.w = fmaxf(0.f, fmaf(h.w, sc.w, sh.w));
    *(float4*)&dout[(size_t)idx * 4] = r;
}

// ---------------- launch -----------------------------------------------------------
extern "C" void kernel_launch(void* const* d_in, const int* in_sizes, int n_in,
                              void* d_out, int out_size) {
    const float* x     = (const float*)d_in[0];
    const float* Wl    = (const float*)d_in[1];
    // d_in[2] = bl : unused — BatchNorm's mean subtraction cancels the bias exactly
    const float* Wr    = (const float*)d_in[3];
    const float* gamma = (const float*)d_in[4];
    const float* beta  = (const float*)d_in[5];
    const int*   ei    = (const int*)d_in[6];   // int32 (JAX x64 disabled)
    const int*   src   = ei;
    const int*   dst   = ei + NE;

    cudaFuncSetAttribute(k_gemm_mma, cudaFuncAttributeMaxDynamicSharedMemorySize,
                         GEMM_SMEM);

    // CSR build (once per call)
    void* cntp = nullptr;
    cudaGetSymbolAddress(&cntp, g_cnt);
    cudaMemsetAsync(cntp, 0, NND * sizeof(int));
    k_hist<<<NE / 256, 256>>>(dst);
    k_scan<<<1, 1024>>>();
    k_scatter<<<NE / 256, 256>>>(src, dst);

    dim3 gemm_grid(NPAD / BM, DD / BN);   // (391, 2)
    for (int l = 0; l < 3; l++) {
        if (l == 0) {
            k_aggregate0<<<NND / 4, 256>>>(x);
            k_mkB<<<(3 * DD * K2) / 256, 256>>>(Wl, Wr);
        } else {
            k_aggregate_fused<<<NND / 4, 256>>>();
        }
        k_gemm_mma<<<gemm_grid, 256, GEMM_SMEM>>>(l);
        k_bnfinal<<<DD, 128>>>(gamma + (size_t)l * DD, beta + (size_t)l * DD);
        if (l == 2) k_apply_out<<<(NND * DD / 4) / 256, 256>>>((float*)d_out);
    }
}

// round 9
// speedup vs baseline: 1.1733x; 1.1733x over previous
#include <cuda_runtime.h>
#include <cuda_bf16.h>
#include <cstdint>

#define NND 50000
#define NPAD 50048
#define NE  800000
#define DD  256
#define K2  512
#define NBP 391              // BN partials = gemm gridDim.x

// GEMM tiling
#define BM 128
#define BN 128
#define CHUNKS 24                 // 3 bf16-split products x (512/64)
#define SROW 144                  // smem row stride bytes (128 data + 16 pad)
#define BUFBYTES (128 * SROW)     // 18432
#define NSTAGE 3
#define STAGEBYTES (2 * BUFBYTES)            // A + B per stage
#define GEMM_SMEM (NSTAGE * STAGEBYTES)      // 110592

// ---------------- static device scratch --------------------------------------
__device__ __align__(16) float g_h[NND * DD];
__device__ __align__(16) float g_x[NND * DD];
__device__ int   g_cnt[NND];
__device__ int   g_rowptr[NND + 1];
__device__ int   g_cursor[NND];
__device__ int   g_csrc[NE];
__device__ float g_invdeg[NND];
__device__ __align__(16) float g_psum[NBP * DD];
__device__ __align__(16) float g_psq[NBP * DD];
__device__ __align__(16) float g_scale[DD];
__device__ __align__(16) float g_shift[DD];
// bf16 split A = [split(agg) | split(x)], rows padded to NPAD (pad rows stay 0)
__device__ __align__(16) __nv_bfloat16 g_ahi[(size_t)NPAD * K2];
__device__ __align__(16) __nv_bfloat16 g_alo[(size_t)NPAD * K2];
// B[n][k] = Wcat[k][n] transposed + split, per layer
__device__ __align__(16) __nv_bfloat16 g_bhi[3][DD * K2];
__device__ __align__(16) __nv_bfloat16 g_blo[3][DD * K2];

__device__ __forceinline__ int clampi(int v, int lo, int hi) {
    return v < lo ? lo : (v > hi ? hi : v);
}
__device__ __forceinline__ uint32_t smem_u32(const void* p) {
    uint32_t a;
    asm("{ .reg .u64 t; cvta.to.shared.u64 t, %1; cvt.u32.u64 %0, t; }" : "=r"(a) : "l"(p));
    return a;
}
__device__ __forceinline__ void ldsm_x4(uint32_t* r, uint32_t addr) {
    asm volatile("ldmatrix.sync.aligned.m8n8.x4.shared.b16 {%0,%1,%2,%3}, [%4];"
        : "=r"(r[0]), "=r"(r[1]), "=r"(r[2]), "=r"(r[3]) : "r"(addr));
}
__device__ __forceinline__ void mma_bf16(float* c, const uint32_t* a,
                                         uint32_t b0, uint32_t b1) {
    asm volatile(
        "mma.sync.aligned.m16n8k16.row.col.f32.bf16.bf16.f32 "
        "{%0,%1,%2,%3}, {%4,%5,%6,%7}, {%8,%9}, {%0,%1,%2,%3};"
        : "+f"(c[0]), "+f"(c[1]), "+f"(c[2]), "+f"(c[3])
        : "r"(a[0]), "r"(a[1]), "r"(a[2]), "r"(a[3]), "r"(b0), "r"(b1));
}
#define CP_ASYNC16(dst, src) \
    asm volatile("cp.async.cg.shared.global [%0], [%1], 16;" :: "r"(dst), "l"(src) : "memory")
#define CP_COMMIT() asm volatile("cp.async.commit_group;" ::: "memory")
#define CP_WAIT(n)  asm volatile("cp.async.wait_group %0;" :: "n"(n) : "memory")

// split helper: v -> (hi, lo) bf16 pair
__device__ __forceinline__ void bf16_split4(const float* v, __nv_bfloat16* hi,
                                            __nv_bfloat16* lo) {
    #pragma unroll
    for (int i = 0; i < 4; i++) {
        hi[i] = __float2bfloat16(v[i]);
        lo[i] = __float2bfloat16(v[i] - __bfloat162float(hi[i]));
    }
}

// ---------------- CSR build ---------------------------------------------------
__global__ void k_hist(const int* __restrict__ dst) {
    int e = blockIdx.x * blockDim.x + threadIdx.x;
    if (e < NE) atomicAdd(&g_cnt[clampi(dst[e], 0, NND - 1)], 1);
}
__global__ void k_scan() {
    __shared__ int s[1024];
    __shared__ int carry;
    int tid = threadIdx.x;
    if (tid == 0) carry = 0;
    __syncthreads();
    for (int base = 0; base < NND; base += 1024) {
        int i = base + tid;
        int v = (i < NND) ? g_cnt[i] : 0;
        s[tid] = v;
        __syncthreads();
        #pragma unroll
        for (int off = 1; off < 1024; off <<= 1) {
            int t = 0;
            if (tid >= off) t = s[tid - off];
            __syncthreads();
            if (tid >= off) s[tid] += t;
            __syncthreads();
        }
        if (i < NND) {
            int rp = carry + s[tid] - v;
            g_rowptr[i] = rp;
            g_cursor[i] = rp;
            g_invdeg[i] = 1.0f / (float)max(v, 1);
        }
        __syncthreads();
        if (tid == 0) carry += s[1023];
        __syncthreads();
    }
    if (tid == 0) g_rowptr[NND] = carry;
}
__global__ void k_scatter(const int* __restrict__ src, const int* __restrict__ dst) {
    int e = blockIdx.x * blockDim.x + threadIdx.x;
    if (e < NE) {
        int d = clampi(dst[e], 0, NND - 1);
        int pos = atomicAdd(&g_cursor[d], 1);
        if (pos >= 0 && pos < NE) g_csrc[pos] = clampi(src[e], 0, NND - 1);
    }
}

// ---------------- mean aggregation + bf16 split (A cols 0-255) -----------------
// 64 threads/node, 4 nodes/block. first: also split x into cols 256-511.
__global__ void __launch_bounds__(256) k_aggregate(const float* __restrict__ xin_param,
                                                   int first) {
    const float* __restrict__ xin = first ? xin_param : g_x;
    int node = blockIdx.x * 4 + (threadIdx.x >> 6);
    int lane = threadIdx.x & 63;
    if (node >= NND) return;
    int beg = g_rowptr[node];
    int end = g_rowptr[node + 1];
    float4 acc = make_float4(0.f, 0.f, 0.f, 0.f);
    for (int e = beg; e < end; e++) {
        int s = g_csrc[e];
        float4 v = *(const float4*)(xin + (size_t)s * DD + lane * 4);
        acc.x += v.x; acc.y += v.y; acc.z += v.z; acc.w += v.w;
    }
    float id = g_invdeg[node];
    float a[4] = { acc.x * id, acc.y * id, acc.z * id, acc.w * id };
    __nv_bfloat16 hi[4], lo[4];
    bf16_split4(a, hi, lo);
    size_t o = (size_t)node * K2 + lane * 4;
    *(uint2*)(g_ahi + o) = *(const uint2*)hi;
    *(uint2*)(g_alo + o) = *(const uint2*)lo;
    if (first) {
        float4 xv = *(const float4*)(xin + (size_t)node * DD + lane * 4);
        float xf[4] = { xv.x, xv.y, xv.z, xv.w };
        bf16_split4(xf, hi, lo);
        *(uint2*)(g_ahi + o + DD) = *(const uint2*)hi;
        *(uint2*)(g_alo + o + DD) = *(const uint2*)lo;
    }
}

// ---------------- weight transpose + split (all 3 layers, once) ----------------
__global__ void __launch_bounds__(256) k_mkB(const float* __restrict__ Wl,
                                             const float* __restrict__ Wr) {
    int idx = blockIdx.x * 256 + threadIdx.x;
    int l = idx / (DD * K2);
    int rem = idx % (DD * K2);
    int n = rem / K2;
    int k = rem % K2;
    float v = (k < DD) ? Wl[(size_t)l * DD * DD + (size_t)k * DD + n]
                       : Wr[(size_t)l * DD * DD + (size_t)(k - DD) * DD + n];
    __nv_bfloat16 hi = __float2bfloat16(v);
    __nv_bfloat16 lo = __float2bfloat16(v - __bfloat162float(hi));
    g_bhi[l][n * K2 + k] = hi;
    g_blo[l][n * K2 + k] = lo;
}

// -------- mma.sync GEMM, 3-stage cp.async pipeline, 1 barrier/chunk ------------
__global__ void __launch_bounds__(256, 2) k_gemm_mma(int layer) {
    extern __shared__ char smem[];

    const int tid  = threadIdx.x;
    const int wid  = tid >> 5;
    const int lane = tid & 31;
    const int wm   = wid >> 1;          // 0..3
    const int wn   = wid & 1;           // 0..1
    const int row0 = blockIdx.x * BM;
    const int col0 = blockIdx.y * BN;

    const __nv_bfloat16* const Asrc[3] = { g_ahi, g_alo, g_ahi };
    const __nv_bfloat16* const Bsrc[3] = { g_bhi[layer], g_bhi[layer], g_blo[layer] };

    const int lrow = tid >> 1;                 // 0..127
    const int lseg = (tid & 1) * 4;            // 16B-seg base (0 or 4)

    float acc[2][8][4];
    #pragma unroll
    for (int i = 0; i < 2; i++)
        #pragma unroll
        for (int j = 0; j < 8; j++)
            #pragma unroll
            for (int q = 0; q < 4; q++) acc[i][j][q] = 0.f;

    // ldmatrix base offsets within a stage
    uint32_t aOff, bOff;
    {
        int am = wm * 32 + (lane & 15);
        int ak = (lane >> 4) * 8;
        int bn = wn * 64 + ((lane >> 4) << 3) + (lane & 7);
        int bk = ((lane >> 3) & 1) * 8;
        aOff = (uint32_t)(am * SROW + ak * 2);
        bOff = (uint32_t)(BUFBYTES + bn * SROW + bk * 2);
    }
    const uint32_t sbase = smem_u32(smem);

    auto load_chunk = [&](int c) {
        int p   = c >> 3;
        int kc  = (c & 7) * 64;
        int st  = c % NSTAGE;
        const __nv_bfloat16* Ag = Asrc[p] + (size_t)(row0 + lrow) * K2 + kc + lseg * 8;
        const __nv_bfloat16* Bg = Bsrc[p] + (size_t)(col0 + lrow) * K2 + kc + lseg * 8;
        uint32_t As = sbase + st * STAGEBYTES + lrow * SROW + lseg * 16;
        uint32_t Bs = As + BUFBYTES;
        #pragma unroll
        for (int i = 0; i < 4; i++) {
            CP_ASYNC16(As + i * 16, Ag + i * 8);
            CP_ASYNC16(Bs + i * 16, Bg + i * 8);
        }
        CP_COMMIT();
    };

    load_chunk(0);
    load_chunk(1);
    for (int c = 0; c < CHUNKS; ++c) {
        if (c + 2 < CHUNKS) CP_WAIT(1); else CP_WAIT(0);
        __syncthreads();              // publishes chunk c; proves chunk c-1 consumed
        if (c + 2 < CHUNKS) load_chunk(c + 2);

        uint32_t stB = sbase + (c % NSTAGE) * STAGEBYTES;
        #pragma unroll
        for (int kk = 0; kk < 64; kk += 16) {
            uint32_t a[2][4], b[4][4];
            #pragma unroll
            for (int mt = 0; mt < 2; mt++)
                ldsm_x4(a[mt], stB + aOff + (mt * 16) * SROW + kk * 2);
            #pragma unroll
            for (int nt = 0; nt < 4; nt++)
                ldsm_x4(b[nt], stB + bOff + (nt * 16) * SROW + kk * 2);
            #pragma unroll
            for (int mi = 0; mi < 2; mi++)
                #pragma unroll
                for (int nj = 0; nj < 8; nj++)
                    mma_bf16(acc[mi][nj], a[mi],
                             b[nj >> 1][(nj & 1) * 2], b[nj >> 1][(nj & 1) * 2 + 1]);
        }
    }

    // --- write h (rows < NND) ---
    const int g  = lane >> 2;
    const int tg = lane & 3;
    #pragma unroll
    for (int mi = 0; mi < 2; mi++) {
        int r1 = row0 + wm * 32 + mi * 16 + g;
        int r2 = r1 + 8;
        #pragma unroll
        for (int nj = 0; nj < 8; nj++) {
            int cix = col0 + wn * 64 + nj * 8 + tg * 2;
            if (r1 < NND) {
                float2 o = { acc[mi][nj][0], acc[mi][nj][1] };
                *(float2*)(g_h + (size_t)r1 * DD + cix) = o;
            }
            if (r2 < NND) {
                float2 o = { acc[mi][nj][2], acc[mi][nj][3] };
                *(float2*)(g_h + (size_t)r2 * DD + cix) = o;
            }
        }
    }

    // --- BN partials: per-CTA column sum & sumsq (pad rows contribute 0) ---
    __syncthreads();                       // reuse stage smem for reduction
    float* sred  = (float*)smem;           // [4][128]
    float* sqred = (float*)(smem + 2048);  // [4][128]
    #pragma unroll
    for (int nj = 0; nj < 8; nj++) {
        float s0 = acc[0][nj][0] + acc[0][nj][2] + acc[1][nj][0] + acc[1][nj][2];
        float s1 = acc[0][nj][1] + acc[0][nj][3] + acc[1][nj][1] + acc[1][nj][3];
        float q0 = acc[0][nj][0]*acc[0][nj][0] + acc[0][nj][2]*acc[0][nj][2]
                 + acc[1][nj][0]*acc[1][nj][0] + acc[1][nj][2]*acc[1][nj][2];
        float q1 = acc[0][nj][1]*acc[0][nj][1] + acc[0][nj][3]*acc[0][nj][3]
                 + acc[1][nj][1]*acc[1][nj][1] + acc[1][nj][3]*acc[1][nj][3];
        #pragma unroll
        for (int off = 16; off >= 4; off >>= 1) {
            s0 += __shfl_down_sync(0xFFFFFFFF, s0, off);
            s1 += __shfl_down_sync(0xFFFFFFFF, s1, off);
            q0 += __shfl_down_sync(0xFFFFFFFF, q0, off);
            q1 += __shfl_down_sync(0xFFFFFFFF, q1, off);
        }
        if (lane < 4) {
            int c = wn * 64 + nj * 8 + lane * 2;
            sred[wm * 128 + c]      = s0;
            sred[wm * 128 + c + 1]  = s1;
            sqred[wm * 128 + c]     = q0;
            sqred[wm * 128 + c + 1] = q1;
        }
    }
    __syncthreads();
    if (tid < 128) {
        float s = sred[tid] + sred[128 + tid] + sred[256 + tid] + sred[384 + tid];
        float q = sqred[tid] + sqred[128 + tid] + sqred[256 + tid] + sqred[384 + tid];
        g_psum[blockIdx.x * DD + col0 + tid] = s;
        g_psq [blockIdx.x * DD + col0 + tid] = q;
    }
}

// ---------------- BN finalize: one block per column -------------------------------
__global__ void __launch_bounds__(128) k_bnfinal(const float* __restrict__ gamma,
                                                 const float* __restrict__ beta) {
    __shared__ float ss[128], sq[128];
    int j = blockIdx.x;          // column
    int t = threadIdx.x;
    float s = 0.f, q = 0.f;
    for (int b = t; b < NBP; b += 128) {
        s += g_psum[b * DD + j];
        q += g_psq[b * DD + j];
    }
    ss[t] = s; sq[t] = q;
    __syncthreads();
    #pragma unroll
    for (int off = 64; off > 0; off >>= 1) {
        if (t < off) { ss[t] += ss[t + off]; sq[t] += sq[t + off]; }
        __syncthreads();
    }
    if (t == 0) {
        float inv_n = 1.0f / (float)NND;
        float mu  = ss[0] * inv_n;
        float var = sq[0] * inv_n - mu * mu;
        float sc  = gamma[j] * rsqrtf(var + 1e-5f);
        g_scale[j] = sc;
        g_shift[j] = beta[j] - mu * sc;
    }
}

// ------- apply BN + ReLU once per node; intermediate layers emit x + split -------
__global__ void __launch_bounds__(256) k_apply(float* __restrict__ dout, int final_layer) {
    int idx = blockIdx.x * blockDim.x + threadIdx.x;   // float4 index
    int r  = idx >> 6;
    int c4 = idx & 63;
    float4 h  = *(const float4*)&g_h[(size_t)idx * 4];
    float4 sc = *(const float4*)&g_scale[c4 * 4];
    float4 sh = *(const float4*)&g_shift[c4 * 4];
    float v[4];
    v[0] = fmaxf(0.f, fmaf(h.x, sc.x, sh.x));
    v[1] = fmaxf(0.f, fmaf(h.y, sc.y, sh.y));
    v[2] = fmaxf(0.f, fmaf(h.z, sc.z, sh.z));
    v[3] = fmaxf(0.f, fmaf(h.w, sc.w, sh.w));
    if (final_layer) {
        *(float4*)&dout[(size_t)idx * 4] = *(const float4*)v;
    } else {
        *(float4*)&g_x[(size_t)idx * 4] = *(const float4*)v;
        __nv_bfloat16 hi[4], lo[4];
        bf16_split4(v, hi, lo);
        size_t o = (size_t)r * K2 + DD + c4 * 4;   // A cols 256-511
        *(uint2*)(g_ahi + o) = *(const uint2*)hi;
        *(uint2*)(g_alo + o) = *(const uint2*)lo;
    }
}

// ---------------- launch -----------------------------------------------------------
extern "C" void kernel_launch(void* const* d_in, const int* in_sizes, int n_in,
                              void* d_out, int out_size) {
    const float* x     = (const float*)d_in[0];
    const float* Wl    = (const float*)d_in[1];
    // d_in[2] = bl : unused — BatchNorm's mean subtraction cancels the bias exactly
    const float* Wr    = (const float*)d_in[3];
    const float* gamma = (const float*)d_in[4];
    const float* beta  = (const float*)d_in[5];
    const int*   ei    = (const int*)d_in[6];   // int32 (JAX x64 disabled)
    const int*   src   = ei;
    const int*   dst   = ei + NE;

    cudaFuncSetAttribute(k_gemm_mma, cudaFuncAttributeMaxDynamicSharedMemorySize,
                         GEMM_SMEM);

    // CSR build (once per call)
    void* cntp = nullptr;
    cudaGetSymbolAddress(&cntp, g_cnt);
    cudaMemsetAsync(cntp, 0, NND * sizeof(int));
    k_hist<<<NE / 256, 256>>>(dst);
    k_scan<<<1, 1024>>>();
    k_scatter<<<NE / 256, 256>>>(src, dst);

    dim3 gemm_grid(NPAD / BM, DD / BN);   // (391, 2)
    for (int l = 0; l < 3; l++) {
        int first = (l == 0) ? 1 : 0;
        k_aggregate<<<NND / 4, 256>>>(x, first);
        if (l == 0) k_mkB<<<(3 * DD * K2) / 256, 256>>>(Wl, Wr);
        k_gemm_mma<<<gemm_grid, 256, GEMM_SMEM>>>(l);
        k_bnfinal<<<DD, 128>>>(gamma + (size_t)l * DD, beta + (size_t)l * DD);
        k_apply<<<(NND * DD / 4) / 256, 256>>>((float*)d_out, (l == 2) ? 1 : 0);
    }
}

// round 10
// speedup vs baseline: 1.5328x; 1.3065x over previous
#include <cuda_runtime.h>
#include <cuda_fp16.h>
#include <cstdint>

#define NND 50000
#define NPAD 50048
#define NE  800000
#define DD  256
#define K2  512
#define NBP 391              // BN partials = gemm gridDim.x

// GEMM tiling
#define BM 128
#define BN 128
#define CHUNKS 16                 // 2 fp16-split products x (512/64)
#define SROW 144                  // smem row stride bytes (128 data + 16 pad)
#define BUFBYTES (128 * SROW)     // 18432
#define GEMM_SMEM (4 * BUFBYTES)  // A0,B0,A1,B1 = 73728

// ---------------- static device scratch --------------------------------------
__device__ __align__(16) float g_h[NND * DD];
__device__ __align__(16) float g_x[NND * DD];
__device__ int   g_cnt[NND];
__device__ int   g_rowptr[NND + 1];
__device__ int   g_cursor[NND];
__device__ int   g_csrc[NE];
__device__ float g_invdeg[NND];
__device__ __align__(16) float g_psum[NBP * DD];
__device__ __align__(16) float g_psq[NBP * DD];
__device__ __align__(16) float g_scale[DD];
__device__ __align__(16) float g_shift[DD];
// fp16 split A = [split(agg) | split(x)], rows padded to NPAD (pad rows stay 0)
__device__ __align__(16) __half g_ahi[(size_t)NPAD * K2];
__device__ __align__(16) __half g_alo[(size_t)NPAD * K2];
// B[n][k] = fp16(Wcat[k][n]) transposed, per layer (residual dropped: 2^-11 rel)
__device__ __align__(16) __half g_bh[3][DD * K2];

__device__ __forceinline__ int clampi(int v, int lo, int hi) {
    return v < lo ? lo : (v > hi ? hi : v);
}
__device__ __forceinline__ uint32_t smem_u32(const void* p) {
    uint32_t a;
    asm("{ .reg .u64 t; cvta.to.shared.u64 t, %1; cvt.u32.u64 %0, t; }" : "=r"(a) : "l"(p));
    return a;
}
__device__ __forceinline__ void ldsm_x4(uint32_t* r, uint32_t addr) {
    asm volatile("ldmatrix.sync.aligned.m8n8.x4.shared.b16 {%0,%1,%2,%3}, [%4];"
        : "=r"(r[0]), "=r"(r[1]), "=r"(r[2]), "=r"(r[3]) : "r"(addr));
}
__device__ __forceinline__ void mma_f16(float* c, const uint32_t* a,
                                        uint32_t b0, uint32_t b1) {
    asm volatile(
        "mma.sync.aligned.m16n8k16.row.col.f32.f16.f16.f32 "
        "{%0,%1,%2,%3}, {%4,%5,%6,%7}, {%8,%9}, {%0,%1,%2,%3};"
        : "+f"(c[0]), "+f"(c[1]), "+f"(c[2]), "+f"(c[3])
        : "r"(a[0]), "r"(a[1]), "r"(a[2]), "r"(a[3]), "r"(b0), "r"(b1));
}
#define CP_ASYNC16(dst, src) \
    asm volatile("cp.async.ca.shared.global [%0], [%1], 16;" :: "r"(dst), "l"(src) : "memory")
#define CP_COMMIT() asm volatile("cp.async.commit_group;" ::: "memory")
#define CP_WAIT(n)  asm volatile("cp.async.wait_group %0;" :: "n"(n) : "memory")

// fp16 Dekker split: v = hi + lo exactly to 2^-22
__device__ __forceinline__ void f16_split4(const float* v, __half* hi, __half* lo) {
    #pragma unroll
    for (int i = 0; i < 4; i++) {
        hi[i] = __float2half_rn(v[i]);
        lo[i] = __float2half_rn(v[i] - __half2float(hi[i]));
    }
}

// ---------------- CSR build ---------------------------------------------------
__global__ void k_hist(const int* __restrict__ dst) {
    int e = blockIdx.x * blockDim.x + threadIdx.x;
    if (e < NE) atomicAdd(&g_cnt[clampi(dst[e], 0, NND - 1)], 1);
}
__global__ void k_scan() {
    __shared__ int s[1024];
    __shared__ int carry;
    int tid = threadIdx.x;
    if (tid == 0) carry = 0;
    __syncthreads();
    for (int base = 0; base < NND; base += 1024) {
        int i = base + tid;
        int v = (i < NND) ? g_cnt[i] : 0;
        s[tid] = v;
        __syncthreads();
        #pragma unroll
        for (int off = 1; off < 1024; off <<= 1) {
            int t = 0;
            if (tid >= off) t = s[tid - off];
            __syncthreads();
            if (tid >= off) s[tid] += t;
            __syncthreads();
        }
        if (i < NND) {
            int rp = carry + s[tid] - v;
            g_rowptr[i] = rp;
            g_cursor[i] = rp;
            g_invdeg[i] = 1.0f / (float)max(v, 1);
        }
        __syncthreads();
        if (tid == 0) carry += s[1023];
        __syncthreads();
    }
    if (tid == 0) g_rowptr[NND] = carry;
}
__global__ void k_scatter(const int* __restrict__ src, const int* __restrict__ dst) {
    int e = blockIdx.x * blockDim.x + threadIdx.x;
    if (e < NE) {
        int d = clampi(dst[e], 0, NND - 1);
        int pos = atomicAdd(&g_cursor[d], 1);
        if (pos >= 0 && pos < NE) g_csrc[pos] = clampi(src[e], 0, NND - 1);
    }
}

// ---------------- mean aggregation + fp16 split (A cols 0-255) -----------------
__global__ void __launch_bounds__(256) k_aggregate(const float* __restrict__ xin_param,
                                                   int first) {
    const float* __restrict__ xin = first ? xin_param : g_x;
    int node = blockIdx.x * 4 + (threadIdx.x >> 6);
    int lane = threadIdx.x & 63;
    if (node >= NND) return;
    int beg = g_rowptr[node];
    int end = g_rowptr[node + 1];
    float4 acc = make_float4(0.f, 0.f, 0.f, 0.f);
    for (int e = beg; e < end; e++) {
        int s = g_csrc[e];
        float4 v = *(const float4*)(xin + (size_t)s * DD + lane * 4);
        acc.x += v.x; acc.y += v.y; acc.z += v.z; acc.w += v.w;
    }
    float id = g_invdeg[node];
    float a[4] = { acc.x * id, acc.y * id, acc.z * id, acc.w * id };
    __half hi[4], lo[4];
    f16_split4(a, hi, lo);
    size_t o = (size_t)node * K2 + lane * 4;
    *(uint2*)(g_ahi + o) = *(const uint2*)hi;
    *(uint2*)(g_alo + o) = *(const uint2*)lo;
    if (first) {
        float4 xv = *(const float4*)(xin + (size_t)node * DD + lane * 4);
        float xf[4] = { xv.x, xv.y, xv.z, xv.w };
        f16_split4(xf, hi, lo);
        *(uint2*)(g_ahi + o + DD) = *(const uint2*)hi;
        *(uint2*)(g_alo + o + DD) = *(const uint2*)lo;
    }
}

// ---------------- weight transpose to fp16 (all 3 layers, once) ----------------
__global__ void __launch_bounds__(256) k_mkB(const float* __restrict__ Wl,
                                             const float* __restrict__ Wr) {
    int idx = blockIdx.x * 256 + threadIdx.x;
    int l = idx / (DD * K2);
    int rem = idx % (DD * K2);
    int n = rem / K2;
    int k = rem % K2;
    float v = (k < DD) ? Wl[(size_t)l * DD * DD + (size_t)k * DD + n]
                       : Wr[(size_t)l * DD * DD + (size_t)(k - DD) * DD + n];
    g_bh[l][n * K2 + k] = __float2half_rn(v);
}

// -------- mma.sync GEMM: h = [Ahi|Alo] @ [Bh;Bh]^T (A exact, B to 2^-11) --------
// R7 structure: 2-stage double buffer, cp.async.ca. BN partials in epilogue.
__global__ void __launch_bounds__(256, 2) k_gemm_mma(int layer) {
    extern __shared__ char smem[];
    char* const Abuf[2] = { smem,            smem + 2 * BUFBYTES };
    char* const Bbuf[2] = { smem + BUFBYTES, smem + 3 * BUFBYTES };

    const int tid  = threadIdx.x;
    const int wid  = tid >> 5;
    const int lane = tid & 31;
    const int wm   = wid >> 1;          // 0..3
    const int wn   = wid & 1;           // 0..1
    const int row0 = blockIdx.x * BM;
    const int col0 = blockIdx.y * BN;

    const __half* const Asrc[2] = { g_ahi, g_alo };
    const __half* const Bh = g_bh[layer];

    const int lrow = tid >> 1;                 // 0..127
    const int lseg = (tid & 1) * 4;            // 16B-seg base (0 or 4)

    float acc[2][8][4];
    #pragma unroll
    for (int i = 0; i < 2; i++)
        #pragma unroll
        for (int j = 0; j < 8; j++)
            #pragma unroll
            for (int q = 0; q < 4; q++) acc[i][j][q] = 0.f;

    uint32_t aLd[2], bLd[2];
    {
        int am = wm * 32 + (lane & 15);
        int ak = (lane >> 4) * 8;
        int bn = wn * 64 + ((lane >> 4) << 3) + (lane & 7);
        int bk = ((lane >> 3) & 1) * 8;
        #pragma unroll
        for (int b = 0; b < 2; b++) {
            aLd[b] = smem_u32(Abuf[b] + am * SROW + ak * 2);
            bLd[b] = smem_u32(Bbuf[b] + bn * SROW + bk * 2);
        }
    }

    auto load_chunk = [&](int c) {
        int p   = c >> 3;
        int kc  = (c & 7) * 64;
        int buf = c & 1;
        const __half* Ag = Asrc[p] + (size_t)(row0 + lrow) * K2 + kc + lseg * 8;
        const __half* Bg = Bh + (size_t)(col0 + lrow) * K2 + kc + lseg * 8;
        uint32_t As = smem_u32(Abuf[buf] + lrow * SROW + lseg * 16);
        uint32_t Bs = smem_u32(Bbuf[buf] + lrow * SROW + lseg * 16);
        #pragma unroll
        for (int i = 0; i < 4; i++) {
            CP_ASYNC16(As + i * 16, Ag + i * 8);
            CP_ASYNC16(Bs + i * 16, Bg + i * 8);
        }
        CP_COMMIT();
    };

    load_chunk(0);
    for (int c = 0; c < CHUNKS; ++c) {
        int buf = c & 1;
        if (c + 1 < CHUNKS) {
            load_chunk(c + 1);
            CP_WAIT(1);
        } else {
            CP_WAIT(0);
        }
        __syncthreads();

        #pragma unroll
        for (int kk = 0; kk < 64; kk += 16) {
            uint32_t a[2][4], b[4][4];
            #pragma unroll
            for (int mt = 0; mt < 2; mt++)
                ldsm_x4(a[mt], aLd[buf] + (mt * 16) * SROW + kk * 2);
            #pragma unroll
            for (int nt = 0; nt < 4; nt++)
                ldsm_x4(b[nt], bLd[buf] + (nt * 16) * SROW + kk * 2);
            #pragma unroll
            for (int mi = 0; mi < 2; mi++)
                #pragma unroll
                for (int nj = 0; nj < 8; nj++)
                    mma_f16(acc[mi][nj], a[mi],
                            b[nj >> 1][(nj & 1) * 2], b[nj >> 1][(nj & 1) * 2 + 1]);
        }
        __syncthreads();
    }

    // --- write h (rows < NND) ---
    const int g  = lane >> 2;
    const int tg = lane & 3;
    #pragma unroll
    for (int mi = 0; mi < 2; mi++) {
        int r1 = row0 + wm * 32 + mi * 16 + g;
        int r2 = r1 + 8;
        #pragma unroll
        for (int nj = 0; nj < 8; nj++) {
            int cix = col0 + wn * 64 + nj * 8 + tg * 2;
            if (r1 < NND) {
                float2 o = { acc[mi][nj][0], acc[mi][nj][1] };
                *(float2*)(g_h + (size_t)r1 * DD + cix) = o;
            }
            if (r2 < NND) {
                float2 o = { acc[mi][nj][2], acc[mi][nj][3] };
                *(float2*)(g_h + (size_t)r2 * DD + cix) = o;
            }
        }
    }

    // --- BN partials: per-CTA column sum & sumsq (pad rows contribute 0) ---
    float* sred  = (float*)smem;            // [4][128]
    float* sqred = (float*)(smem + 2048);   // [4][128]
    #pragma unroll
    for (int nj = 0; nj < 8; nj++) {
        float s0 = acc[0][nj][0] + acc[0][nj][2] + acc[1][nj][0] + acc[1][nj][2];
        float s1 = acc[0][nj][1] + acc[0][nj][3] + acc[1][nj][1] + acc[1][nj][3];
        float q0 = acc[0][nj][0]*acc[0][nj][0] + acc[0][nj][2]*acc[0][nj][2]
                 + acc[1][nj][0]*acc[1][nj][0] + acc[1][nj][2]*acc[1][nj][2];
        float q1 = acc[0][nj][1]*acc[0][nj][1] + acc[0][nj][3]*acc[0][nj][3]
                 + acc[1][nj][1]*acc[1][nj][1] + acc[1][nj][3]*acc[1][nj][3];
        #pragma unroll
        for (int off = 16; off >= 4; off >>= 1) {
            s0 += __shfl_down_sync(0xFFFFFFFF, s0, off);
            s1 += __shfl_down_sync(0xFFFFFFFF, s1, off);
            q0 += __shfl_down_sync(0xFFFFFFFF, q0, off);
            q1 += __shfl_down_sync(0xFFFFFFFF, q1, off);
        }
        if (lane < 4) {
            int c = wn * 64 + nj * 8 + lane * 2;
            sred[wm * 128 + c]      = s0;
            sred[wm * 128 + c + 1]  = s1;
            sqred[wm * 128 + c]     = q0;
            sqred[wm * 128 + c + 1] = q1;
        }
    }
    __syncthreads();
    if (tid < 128) {
        float s = sred[tid] + sred[128 + tid] + sred[256 + tid] + sred[384 + tid];
        float q = sqred[tid] + sqred[128 + tid] + sqred[256 + tid] + sqred[384 + tid];
        g_psum[blockIdx.x * DD + col0 + tid] = s;
        g_psq [blockIdx.x * DD + col0 + tid] = q;
    }
}

// ---------------- BN finalize: one block per column -------------------------------
__global__ void __launch_bounds__(128) k_bnfinal(const float* __restrict__ gamma,
                                                 const float* __restrict__ beta) {
    __shared__ float ss[128], sq[128];
    int j = blockIdx.x;          // column
    int t = threadIdx.x;
    float s = 0.f, q = 0.f;
    for (int b = t; b < NBP; b += 128) {
        s += g_psum[b * DD + j];
        q += g_psq[b * DD + j];
    }
    ss[t] = s; sq[t] = q;
    __syncthreads();
    #pragma unroll
    for (int off = 64; off > 0; off >>= 1) {
        if (t < off) { ss[t] += ss[t + off]; sq[t] += sq[t + off]; }
        __syncthreads();
    }
    if (t == 0) {
        float inv_n = 1.0f / (float)NND;
        float mu  = ss[0] * inv_n;
        float var = sq[0] * inv_n - mu * mu;
        float sc  = gamma[j] * rsqrtf(var + 1e-5f);
        g_scale[j] = sc;
        g_shift[j] = beta[j] - mu * sc;
    }
}

// ------- apply BN + ReLU once per node; intermediate layers emit x + split -------
__global__ void __launch_bounds__(256) k_apply(float* __restrict__ dout, int final_layer) {
    int idx = blockIdx.x * blockDim.x + threadIdx.x;   // float4 index
    int r  = idx >> 6;
    int c4 = idx & 63;
    float4 h  = *(const float4*)&g_h[(size_t)idx * 4];
    float4 sc = *(const float4*)&g_scale[c4 * 4];
    float4 sh = *(const float4*)&g_shift[c4 * 4];
    float v[4];
    v[0] = fmaxf(0.f, fmaf(h.x, sc.x, sh.x));
    v[1] = fmaxf(0.f, fmaf(h.y, sc.y, sh.y));
    v[2] = fmaxf(0.f, fmaf(h.z, sc.z, sh.z));
    v[3] = fmaxf(0.f, fmaf(h.w, sc.w, sh.w));
    if (final_layer) {
        *(float4*)&dout[(size_t)idx * 4] = *(const float4*)v;
    } else {
        *(float4*)&g_x[(size_t)idx * 4] = *(const float4*)v;
        __half hi[4], lo[4];
        f16_split4(v, hi, lo);
        size_t o = (size_t)r * K2 + DD + c4 * 4;   // A cols 256-511
        *(uint2*)(g_ahi + o) = *(const uint2*)hi;
        *(uint2*)(g_alo + o) = *(const uint2*)lo;
    }
}

// ---------------- launch -----------------------------------------------------------
extern "C" void kernel_launch(void* const* d_in, const int* in_sizes, int n_in,
                              void* d_out, int out_size) {
    const float* x     = (const float*)d_in[0];
    const float* Wl    = (const float*)d_in[1];
    // d_in[2] = bl : unused — BatchNorm's mean subtraction cancels the bias exactly
    const float* Wr    = (const float*)d_in[3];
    const float* gamma = (const float*)d_in[4];
    const float* beta  = (const float*)d_in[5];
    const int*   ei    = (const int*)d_in[6];   // int32 (JAX x64 disabled)
    const int*   src   = ei;
    const int*   dst   = ei + NE;

    cudaFuncSetAttribute(k_gemm_mma, cudaFuncAttributeMaxDynamicSharedMemorySize,
                         GEMM_SMEM);

    // CSR build (once per call)
    void* cntp = nullptr;
    cudaGetSymbolAddress(&cntp, g_cnt);
    cudaMemsetAsync(cntp, 0, NND * sizeof(int));
    k_hist<<<NE / 256, 256>>>(dst);
    k_scan<<<1, 1024>>>();
    k_scatter<<<NE / 256, 256>>>(src, dst);

    dim3 gemm_grid(NPAD / BM, DD / BN);   // (391, 2)
    for (int l = 0; l < 3; l++) {
        int first = (l == 0) ? 1 : 0;
        k_aggregate<<<NND / 4, 256>>>(x, first);
        if (l == 0) k_mkB<<<(3 * DD * K2) / 256, 256>>>(Wl, Wr);
        k_gemm_mma<<<gemm_grid, 256, GEMM_SMEM>>>(l);
        k_bnfinal<<<DD, 128>>>(gamma + (size_t)l * DD, beta + (size_t)l * DD);
        k_apply<<<(NND * DD / 4) / 256, 256>>>((float*)d_out, (l == 2) ? 1 : 0);
    }
}

// round 11
// speedup vs baseline: 2.1890x; 1.4280x over previous
#include <cuda_runtime.h>
#include <cuda_fp16.h>
#include <cstdint>

#define NND 50000
#define NPAD 50048
#define NE  800000
#define DD  256
#define K2  512
#define NBP 391              // BN partials = gemm gridDim.x

// GEMM tiling
#define BM 128
#define BN 128
#define CHUNKS 8                  // K=512 / 64, single fp16 product
#define SROW 144                  // smem row stride bytes (128 data + 16 pad)
#define BUFBYTES (128 * SROW)     // 18432
#define GEMM_SMEM (4 * BUFBYTES)  // A0,B0,A1,B1 = 73728

// ---------------- static device scratch --------------------------------------
__device__ __align__(16) float g_h[NND * DD];
__device__ int   g_cnt[NND];
__device__ int   g_rowptr[NND + 1];
__device__ int   g_cursor[NND];
__device__ int   g_csrc[NE];
__device__ float g_invdeg[NND];
__device__ __align__(16) float g_psum[NBP * DD];
__device__ __align__(16) float g_psq[NBP * DD];
__device__ __align__(16) float g_scale[DD];
__device__ __align__(16) float g_shift[DD];
// fp16 A = [fp16(agg) | fp16(x)], rows padded to NPAD (pad rows stay 0)
__device__ __align__(16) __half g_a[(size_t)NPAD * K2];
// B[n][k] = fp16(Wcat[k][n]) transposed, per layer
__device__ __align__(16) __half g_bh[3][DD * K2];

__device__ __forceinline__ int clampi(int v, int lo, int hi) {
    return v < lo ? lo : (v > hi ? hi : v);
}
__device__ __forceinline__ uint32_t smem_u32(const void* p) {
    uint32_t a;
    asm("{ .reg .u64 t; cvta.to.shared.u64 t, %1; cvt.u32.u64 %0, t; }" : "=r"(a) : "l"(p));
    return a;
}
__device__ __forceinline__ void ldsm_x4(uint32_t* r, uint32_t addr) {
    asm volatile("ldmatrix.sync.aligned.m8n8.x4.shared.b16 {%0,%1,%2,%3}, [%4];"
        : "=r"(r[0]), "=r"(r[1]), "=r"(r[2]), "=r"(r[3]) : "r"(addr));
}
__device__ __forceinline__ void mma_f16(float* c, const uint32_t* a,
                                        uint32_t b0, uint32_t b1) {
    asm volatile(
        "mma.sync.aligned.m16n8k16.row.col.f32.f16.f16.f32 "
        "{%0,%1,%2,%3}, {%4,%5,%6,%7}, {%8,%9}, {%0,%1,%2,%3};"
        : "+f"(c[0]), "+f"(c[1]), "+f"(c[2]), "+f"(c[3])
        : "r"(a[0]), "r"(a[1]), "r"(a[2]), "r"(a[3]), "r"(b0), "r"(b1));
}
#define CP_ASYNC16(dst, src) \
    asm volatile("cp.async.ca.shared.global [%0], [%1], 16;" :: "r"(dst), "l"(src) : "memory")
#define CP_COMMIT() asm volatile("cp.async.commit_group;" ::: "memory")
#define CP_WAIT(n)  asm volatile("cp.async.wait_group %0;" :: "n"(n) : "memory")

// ---------------- CSR build ---------------------------------------------------
__global__ void k_hist(const int* __restrict__ dst) {
    int e = blockIdx.x * blockDim.x + threadIdx.x;
    if (e < NE) atomicAdd(&g_cnt[clampi(dst[e], 0, NND - 1)], 1);
}
__global__ void k_scan() {
    __shared__ int s[1024];
    __shared__ int carry;
    int tid = threadIdx.x;
    if (tid == 0) carry = 0;
    __syncthreads();
    for (int base = 0; base < NND; base += 1024) {
        int i = base + tid;
        int v = (i < NND) ? g_cnt[i] : 0;
        s[tid] = v;
        __syncthreads();
        #pragma unroll
        for (int off = 1; off < 1024; off <<= 1) {
            int t = 0;
            if (tid >= off) t = s[tid - off];
            __syncthreads();
            if (tid >= off) s[tid] += t;
            __syncthreads();
        }
        if (i < NND) {
            int rp = carry + s[tid] - v;
            g_rowptr[i] = rp;
            g_cursor[i] = rp;
            g_invdeg[i] = 1.0f / (float)max(v, 1);
        }
        __syncthreads();
        if (tid == 0) carry += s[1023];
        __syncthreads();
    }
    if (tid == 0) g_rowptr[NND] = carry;
}
__global__ void k_scatter(const int* __restrict__ src, const int* __restrict__ dst) {
    int e = blockIdx.x * blockDim.x + threadIdx.x;
    if (e < NE) {
        int d = clampi(dst[e], 0, NND - 1);
        int pos = atomicAdd(&g_cursor[d], 1);
        if (pos >= 0 && pos < NE) g_csrc[pos] = clampi(src[e], 0, NND - 1);
    }
}

// -------- layer-0 aggregate: gather fp32 x, write fp16 agg + fp16 x ------------
__global__ void __launch_bounds__(256) k_aggregate0(const float* __restrict__ xin) {
    int node = blockIdx.x * 4 + (threadIdx.x >> 6);
    int lane = threadIdx.x & 63;
    if (node >= NND) return;
    int beg = g_rowptr[node];
    int end = g_rowptr[node + 1];
    float4 acc = make_float4(0.f, 0.f, 0.f, 0.f);
    for (int e = beg; e < end; e++) {
        int s = g_csrc[e];
        float4 v = *(const float4*)(xin + (size_t)s * DD + lane * 4);
        acc.x += v.x; acc.y += v.y; acc.z += v.z; acc.w += v.w;
    }
    float id = g_invdeg[node];
    __half h4[4];
    h4[0] = __float2half_rn(acc.x * id);
    h4[1] = __float2half_rn(acc.y * id);
    h4[2] = __float2half_rn(acc.z * id);
    h4[3] = __float2half_rn(acc.w * id);
    size_t o = (size_t)node * K2 + lane * 4;
    *(uint2*)(g_a + o) = *(const uint2*)h4;
    float4 xv = *(const float4*)(xin + (size_t)node * DD + lane * 4);
    h4[0] = __float2half_rn(xv.x);
    h4[1] = __float2half_rn(xv.y);
    h4[2] = __float2half_rn(xv.z);
    h4[3] = __float2half_rn(xv.w);
    *(uint2*)(g_a + o + DD) = *(const uint2*)h4;
}

// -------- layers 1,2 aggregate: gather fp16 x (cols 256-511), fp32 accum -------
__global__ void __launch_bounds__(256) k_aggregate_h() {
    int node = blockIdx.x * 4 + (threadIdx.x >> 6);
    int lane = threadIdx.x & 63;
    if (node >= NND) return;
    int beg = g_rowptr[node];
    int end = g_rowptr[node + 1];
    float acc0 = 0.f, acc1 = 0.f, acc2 = 0.f, acc3 = 0.f;
    for (int e = beg; e < end; e++) {
        int s = g_csrc[e];
        uint2 raw = *(const uint2*)(g_a + (size_t)s * K2 + DD + lane * 4);
        __half2 p0 = *(const __half2*)&raw.x;
        __half2 p1 = *(const __half2*)&raw.y;
        float2 f0 = __half22float2(p0);
        float2 f1 = __half22float2(p1);
        acc0 += f0.x; acc1 += f0.y; acc2 += f1.x; acc3 += f1.y;
    }
    float id = g_invdeg[node];
    __half h4[4];
    h4[0] = __float2half_rn(acc0 * id);
    h4[1] = __float2half_rn(acc1 * id);
    h4[2] = __float2half_rn(acc2 * id);
    h4[3] = __float2half_rn(acc3 * id);
    *(uint2*)(g_a + (size_t)node * K2 + lane * 4) = *(const uint2*)h4;
}

// ---------------- weight transpose to fp16 (all 3 layers, once) ----------------
__global__ void __launch_bounds__(256) k_mkB(const float* __restrict__ Wl,
                                             const float* __restrict__ Wr) {
    int idx = blockIdx.x * 256 + threadIdx.x;
    int l = idx / (DD * K2);
    int rem = idx % (DD * K2);
    int n = rem / K2;
    int k = rem % K2;
    float v = (k < DD) ? Wl[(size_t)l * DD * DD + (size_t)k * DD + n]
                       : Wr[(size_t)l * DD * DD + (size_t)(k - DD) * DD + n];
    g_bh[l][n * K2 + k] = __float2half_rn(v);
}

// -------- mma.sync GEMM: h = fp16(A) @ fp16(B)^T, fp32 accum --------------------
__global__ void __launch_bounds__(256, 2) k_gemm_mma(int layer) {
    extern __shared__ char smem[];
    char* const Abuf[2] = { smem,            smem + 2 * BUFBYTES };
    char* const Bbuf[2] = { smem + BUFBYTES, smem + 3 * BUFBYTES };

    const int tid  = threadIdx.x;
    const int wid  = tid >> 5;
    const int lane = tid & 31;
    const int wm   = wid >> 1;          // 0..3
    const int wn   = wid & 1;           // 0..1
    const int row0 = blockIdx.x * BM;
    const int col0 = blockIdx.y * BN;

    const __half* const Bh = g_bh[layer];

    const int lrow = tid >> 1;                 // 0..127
    const int lseg = (tid & 1) * 4;            // 16B-seg base (0 or 4)

    float acc[2][8][4];
    #pragma unroll
    for (int i = 0; i < 2; i++)
        #pragma unroll
        for (int j = 0; j < 8; j++)
            #pragma unroll
            for (int q = 0; q < 4; q++) acc[i][j][q] = 0.f;

    uint32_t aLd[2], bLd[2];
    {
        int am = wm * 32 + (lane & 15);
        int ak = (lane >> 4) * 8;
        int bn = wn * 64 + ((lane >> 4) << 3) + (lane & 7);
        int bk = ((lane >> 3) & 1) * 8;
        #pragma unroll
        for (int b = 0; b < 2; b++) {
            aLd[b] = smem_u32(Abuf[b] + am * SROW + ak * 2);
            bLd[b] = smem_u32(Bbuf[b] + bn * SROW + bk * 2);
        }
    }

    auto load_chunk = [&](int c) {
        int kc  = c * 64;
        int buf = c & 1;
        const __half* Ag = g_a + (size_t)(row0 + lrow) * K2 + kc + lseg * 8;
        const __half* Bg = Bh + (size_t)(col0 + lrow) * K2 + kc + lseg * 8;
        uint32_t As = smem_u32(Abuf[buf] + lrow * SROW + lseg * 16);
        uint32_t Bs = smem_u32(Bbuf[buf] + lrow * SROW + lseg * 16);
        #pragma unroll
        for (int i = 0; i < 4; i++) {
            CP_ASYNC16(As + i * 16, Ag + i * 8);
            CP_ASYNC16(Bs + i * 16, Bg + i * 8);
        }
        CP_COMMIT();
    };

    load_chunk(0);
    for (int c = 0; c < CHUNKS; ++c) {
        int buf = c & 1;
        if (c + 1 < CHUNKS) {
            load_chunk(c + 1);
            CP_WAIT(1);
        } else {
            CP_WAIT(0);
        }
        __syncthreads();

        #pragma unroll
        for (int kk = 0; kk < 64; kk += 16) {
            uint32_t a[2][4], b[4][4];
            #pragma unroll
            for (int mt = 0; mt < 2; mt++)
                ldsm_x4(a[mt], aLd[buf] + (mt * 16) * SROW + kk * 2);
            #pragma unroll
            for (int nt = 0; nt < 4; nt++)
                ldsm_x4(b[nt], bLd[buf] + (nt * 16) * SROW + kk * 2);
            #pragma unroll
            for (int mi = 0; mi < 2; mi++)
                #pragma unroll
                for (int nj = 0; nj < 8; nj++)
                    mma_f16(acc[mi][nj], a[mi],
                            b[nj >> 1][(nj & 1) * 2], b[nj >> 1][(nj & 1) * 2 + 1]);
        }
        __syncthreads();
    }

    // --- write h (rows < NND) ---
    const int g  = lane >> 2;
    const int tg = lane & 3;
    #pragma unroll
    for (int mi = 0; mi < 2; mi++) {
        int r1 = row0 + wm * 32 + mi * 16 + g;
        int r2 = r1 + 8;
        #pragma unroll
        for (int nj = 0; nj < 8; nj++) {
            int cix = col0 + wn * 64 + nj * 8 + tg * 2;
            if (r1 < NND) {
                float2 o = { acc[mi][nj][0], acc[mi][nj][1] };
                *(float2*)(g_h + (size_t)r1 * DD + cix) = o;
            }
            if (r2 < NND) {
                float2 o = { acc[mi][nj][2], acc[mi][nj][3] };
                *(float2*)(g_h + (size_t)r2 * DD + cix) = o;
            }
        }
    }

    // --- BN partials: per-CTA column sum & sumsq (pad rows contribute 0) ---
    float* sred  = (float*)smem;            // [4][128]
    float* sqred = (float*)(smem + 2048);   // [4][128]
    #pragma unroll
    for (int nj = 0; nj < 8; nj++) {
        float s0 = acc[0][nj][0] + acc[0][nj][2] + acc[1][nj][0] + acc[1][nj][2];
        float s1 = acc[0][nj][1] + acc[0][nj][3] + acc[1][nj][1] + acc[1][nj][3];
        float q0 = acc[0][nj][0]*acc[0][nj][0] + acc[0][nj][2]*acc[0][nj][2]
                 + acc[1][nj][0]*acc[1][nj][0] + acc[1][nj][2]*acc[1][nj][2];
        float q1 = acc[0][nj][1]*acc[0][nj][1] + acc[0][nj][3]*acc[0][nj][3]
                 + acc[1][nj][1]*acc[1][nj][1] + acc[1][nj][3]*acc[1][nj][3];
        #pragma unroll
        for (int off = 16; off >= 4; off >>= 1) {
            s0 += __shfl_down_sync(0xFFFFFFFF, s0, off);
            s1 += __shfl_down_sync(0xFFFFFFFF, s1, off);
            q0 += __shfl_down_sync(0xFFFFFFFF, q0, off);
            q1 += __shfl_down_sync(0xFFFFFFFF, q1, off);
        }
        if (lane < 4) {
            int c = wn * 64 + nj * 8 + lane * 2;
            sred[wm * 128 + c]      = s0;
            sred[wm * 128 + c + 1]  = s1;
            sqred[wm * 128 + c]     = q0;
            sqred[wm * 128 + c + 1] = q1;
        }
    }
    __syncthreads();
    if (tid < 128) {
        float s = sred[tid] + sred[128 + tid] + sred[256 + tid] + sred[384 + tid];
        float q = sqred[tid] + sqred[128 + tid] + sqred[256 + tid] + sqred[384 + tid];
        g_psum[blockIdx.x * DD + col0 + tid] = s;
        g_psq [blockIdx.x * DD + col0 + tid] = q;
    }
}

// ---------------- BN finalize: one block per column -------------------------------
__global__ void __launch_bounds__(128) k_bnfinal(const float* __restrict__ gamma,
                                                 const float* __restrict__ beta) {
    __shared__ float ss[128], sq[128];
    int j = blockIdx.x;          // column
    int t = threadIdx.x;
    float s = 0.f, q = 0.f;
    for (int b = t; b < NBP; b += 128) {
        s += g_psum[b * DD + j];
        q += g_psq[b * DD + j];
    }
    ss[t] = s; sq[t] = q;
    __syncthreads();
    #pragma unroll
    for (int off = 64; off > 0; off >>= 1) {
        if (t < off) { ss[t] += ss[t + off]; sq[t] += sq[t + off]; }
        __syncthreads();
    }
    if (t == 0) {
        float inv_n = 1.0f / (float)NND;
        float mu  = ss[0] * inv_n;
        float var = sq[0] * inv_n - mu * mu;
        float sc  = gamma[j] * rsqrtf(var + 1e-5f);
        g_scale[j] = sc;
        g_shift[j] = beta[j] - mu * sc;
    }
}

// ------- apply BN + ReLU once per node; intermediate layers emit fp16 x ---------
__global__ void __launch_bounds__(256) k_apply(float* __restrict__ dout, int final_layer) {
    int idx = blockIdx.x * blockDim.x + threadIdx.x;   // float4 index
    int r  = idx >> 6;
    int c4 = idx & 63;
    float4 h  = *(const float4*)&g_h[(size_t)idx * 4];
    float4 sc = *(const float4*)&g_scale[c4 * 4];
    float4 sh = *(const float4*)&g_shift[c4 * 4];
    float v[4];
    v[0] = fmaxf(0.f, fmaf(h.x, sc.x, sh.x));
    v[1] = fmaxf(0.f, fmaf(h.y, sc.y, sh.y));
    v[2] = fmaxf(0.f, fmaf(h.z, sc.z, sh.z));
    v[3] = fmaxf(0.f, fmaf(h.w, sc.w, sh.w));
    if (final_layer) {
        *(float4*)&dout[(size_t)idx * 4] = *(const float4*)v;
    } else {
        __half h4[4];
        h4[0] = __float2half_rn(v[0]);
        h4[1] = __float2half_rn(v[1]);
        h4[2] = __float2half_rn(v[2]);
        h4[3] = __float2half_rn(v[3]);
        size_t o = (size_t)r * K2 + DD + c4 * 4;   // A cols 256-511
        *(uint2*)(g_a + o) = *(const uint2*)h4;
    }
}

// ---------------- launch -----------------------------------------------------------
extern "C" void kernel_launch(void* const* d_in, const int* in_sizes, int n_in,
                              void* d_out, int out_size) {
    const float* x     = (const float*)d_in[0];
    const float* Wl    = (const float*)d_in[1];
    // d_in[2] = bl : unused — BatchNorm's mean subtraction cancels the bias exactly
    const float* Wr    = (const float*)d_in[3];
    const float* gamma = (const float*)d_in[4];
    const float* beta  = (const float*)d_in[5];
    const int*   ei    = (const int*)d_in[6];   // int32 (JAX x64 disabled)
    const int*   src   = ei;
    const int*   dst   = ei + NE;

    cudaFuncSetAttribute(k_gemm_mma, cudaFuncAttributeMaxDynamicSharedMemorySize,
                         GEMM_SMEM);

    // CSR build (once per call)
    void* cntp = nullptr;
    cudaGetSymbolAddress(&cntp, g_cnt);
    cudaMemsetAsync(cntp, 0, NND * sizeof(int));
    k_hist<<<NE / 256, 256>>>(dst);
    k_scan<<<1, 1024>>>();
    k_scatter<<<NE / 256, 256>>>(src, dst);

    dim3 gemm_grid(NPAD / BM, DD / BN);   // (391, 2)
    for (int l = 0; l < 3; l++) {
        if (l == 0) {
            k_aggregate0<<<NND / 4, 256>>>(x);
            k_mkB<<<(3 * DD * K2) / 256, 256>>>(Wl, Wr);
        } else {
            k_aggregate_h<<<NND / 4, 256>>>();
        }
        k_gemm_mma<<<gemm_grid, 256, GEMM_SMEM>>>(l);
        k_bnfinal<<<DD, 128>>>(gamma + (size_t)l * DD, beta + (size_t)l * DD);
        k_apply<<<(NND * DD / 4) / 256, 256>>>((float*)d_out, (l == 2) ? 1 : 0);
    }
}